// round 15
// baseline (speedup 1.0000x reference)
#include <cuda_runtime.h>
#include <cuda_fp16.h>
#include <cstdint>

#define N_NODES 50000
#define D 128
#define NE 800000
#define BM 128
#define ASTRIDE 136                              // halfs per smem row
#define TILE_B (128 * ASTRIDE * 2)               // 34816 bytes per 128x128 fp16 tile
#define GEMM_SMEM (3 * TILE_B)                   // A, Wh, Wl
#define MLP_SMEM  (5 * TILE_B)                   // A/B, W1h, W1l, W2h, W2l
#define CHUNK 49                                  // scan chunk (49*1024 >= 50000)

// -------- shared compute scratch (graphs run sequentially) --------
__device__ __half g_h[(size_t)N_NODES * D];     // hs = (A@W)*dis[row]
__device__ __half g_buf[(size_t)N_NODES * D];   // layer activations, fp16
// -------- per-graph CSR scratch (builds overlap) --------
__device__ float  g_dis[2][N_NODES];
__device__ int    g_cnt[2][N_NODES];
__device__ int    g_off[2][N_NODES];
__device__ int    g_cur[2][N_NODES];
__device__ int    g_csrc[2][NE];
// -------- packed weights: 5 x [hi 128x128][lo 128x128] fp16, layout [n][k] --------
__device__ __half g_wt[5 * 2 * 16384];

// -------- CSR build --------
__global__ void zero_kernel(int* __restrict__ cnt) {
    int i = blockIdx.x * blockDim.x + threadIdx.x;
    if (i < N_NODES) cnt[i] = 0;
}
__global__ void count_kernel(const int* __restrict__ dst, int* __restrict__ cnt) {
    int e = blockIdx.x * blockDim.x + threadIdx.x;
    if (e < NE) atomicAdd(&cnt[dst[e]], 1);
}
// single-block fused scan: off = exclusive_scan(cnt); cur = off; dis = rsqrt(cnt+1)
__global__ __launch_bounds__(1024, 1)
void scan_fused_kernel(const int* __restrict__ cnt, int* __restrict__ off,
                       int* __restrict__ cur, float* __restrict__ dis) {
    __shared__ int sh[1024];
    int t = threadIdx.x;
    int base = t * CHUNK;
    int sum = 0;
    for (int i = 0; i < CHUNK; i++) {
        int idx = base + i;
        if (idx < N_NODES) sum += cnt[idx];
    }
    sh[t] = sum;
    __syncthreads();
#pragma unroll
    for (int ofs = 1; ofs < 1024; ofs <<= 1) {
        int v = (t >= ofs) ? sh[t - ofs] : 0;
        __syncthreads();
        sh[t] += v;
        __syncthreads();
    }
    int prefix = sh[t] - sum;   // exclusive
    for (int i = 0; i < CHUNK; i++) {
        int idx = base + i;
        if (idx < N_NODES) {
            int c = cnt[idx];
            off[idx] = prefix;
            cur[idx] = prefix;
            dis[idx] = rsqrtf((float)c + 1.0f);
            prefix += c;
        }
    }
}
__global__ void fill_kernel(const int* __restrict__ src, const int* __restrict__ dst,
                            int* __restrict__ cur, int* __restrict__ csrc) {
    int e = blockIdx.x * blockDim.x + threadIdx.x;
    if (e >= NE) return;
    int p = atomicAdd(&cur[dst[e]], 1);
    csrc[p] = src[e];
}

// -------- weight prep: W[k][n] fp32 -> Wt_hi[n][k], Wt_lo[n][k] fp16 --------
__global__ void wprep_kernel(const float* __restrict__ W0, const float* __restrict__ W1,
                             const float* __restrict__ W2, const float* __restrict__ W3,
                             const float* __restrict__ W4) {
    int idx = blockIdx.x * blockDim.x + threadIdx.x;
    if (idx >= 5 * 16384) return;
    int w = idx >> 14;
    int p = idx & 16383;
    int n = p >> 7;
    int k = p & 127;
    const float* W = (w == 0) ? W0 : (w == 1) ? W1 : (w == 2) ? W2 : (w == 3) ? W3 : W4;
    float v = __ldg(&W[k * 128 + n]);
    __half hi = __float2half_rn(v);
    __half lo = __float2half_rn(v - __half2float(hi));
    g_wt[(size_t)w * 32768 + n * 128 + k]         = hi;
    g_wt[(size_t)w * 32768 + 16384 + n * 128 + k] = lo;
}

// -------- f16 mma.sync (baseline sm_80+ PTX) --------
__device__ __forceinline__ void mma_f16(float* c, const uint32_t* a, const uint32_t* b) {
    asm volatile(
        "mma.sync.aligned.m16n8k16.row.col.f32.f16.f16.f32 "
        "{%0,%1,%2,%3}, {%4,%5,%6,%7}, {%8,%9}, {%0,%1,%2,%3};\n"
        : "+f"(c[0]), "+f"(c[1]), "+f"(c[2]), "+f"(c[3])
        : "r"(a[0]), "r"(a[1]), "r"(a[2]), "r"(a[3]), "r"(b[0]), "r"(b[1]));
}

// load A tile into smem [128][ASTRIDE] fp16; fp32 input converts, fp16 copies
__device__ __forceinline__ void load_a_tile(__half* Ah, const void* A, int a_fp16,
                                            int m0, int M, int tid) {
    if (a_fp16) {
        const __half* Af = (const __half*)A;
#pragma unroll
        for (int i = 0; i < 8; i++) {
            int f   = i * 256 + tid;       // 2048 uint4
            int m   = f >> 4;
            int c16 = f & 15;
            uint4 v = make_uint4(0, 0, 0, 0);
            if (m0 + m < M)
                v = __ldg((const uint4*)(Af + (size_t)(m0 + m) * D) + c16);
            *(uint4*)((char*)Ah + m * (ASTRIDE * 2) + c16 * 16) = v;
        }
    } else {
        const float* Af = (const float*)A;
#pragma unroll
        for (int i = 0; i < 16; i++) {
            int f  = i * 256 + tid;        // 4096 float4
            int m  = f >> 5;
            int k4 = f & 31;
            float4 v = make_float4(0.f, 0.f, 0.f, 0.f);
            if (m0 + m < M) v = __ldg((const float4*)(Af + (size_t)(m0 + m) * D) + k4);
            __half2 h0 = __floats2half2_rn(v.x, v.y);
            __half2 h1 = __floats2half2_rn(v.z, v.w);
            uint2 pk;
            pk.x = *(uint32_t*)&h0; pk.y = *(uint32_t*)&h1;
            *(uint2*)((char*)Ah + m * (ASTRIDE * 2) + k4 * 8) = pk;
        }
    }
}
// copy one 128x128 fp16 weight tile into padded smem
__device__ __forceinline__ void load_w_tile(__half* Ws, const __half* Wt, int tid) {
#pragma unroll
    for (int i = 0; i < 8; i++) {
        int f   = i * 256 + tid;
        int n   = f >> 4;
        int c16 = f & 15;
        *(uint4*)((char*)Ws + n * (ASTRIDE * 2) + c16 * 16) =
            __ldg((const uint4*)((const char*)Wt + n * 256 + c16 * 16));
    }
}
// MMA sweep: acc += A_tile @ W_tile^T fragments for this warp's 32x64 region
__device__ __forceinline__ void mma_sweep(float acc[2][8][4], const __half* Ah,
                                          const __half* Wh, const __half* Wl,
                                          int rbase, int nbase, int gr, int qc) {
#pragma unroll
    for (int kc = 0; kc < 8; kc++) {
        int k0 = kc * 16;
        uint32_t aF[2][4];
#pragma unroll
        for (int rt = 0; rt < 2; rt++) {
            const __half* ph = Ah + (rbase + rt * 16 + gr) * ASTRIDE + k0 + qc;
            aF[rt][0] = *(const uint32_t*)ph;
            aF[rt][1] = *(const uint32_t*)(ph + 8 * ASTRIDE);
            aF[rt][2] = *(const uint32_t*)(ph + 8);
            aF[rt][3] = *(const uint32_t*)(ph + 8 * ASTRIDE + 8);
        }
#pragma unroll
        for (int ct = 0; ct < 8; ct++) {
            int n = nbase + ct * 8 + gr;
            const __half* ph = Wh + n * ASTRIDE + k0 + qc;
            const __half* pl = Wl + n * ASTRIDE + k0 + qc;
            uint32_t bH[2] = {*(const uint32_t*)ph, *(const uint32_t*)(ph + 8)};
            uint32_t bL[2] = {*(const uint32_t*)pl, *(const uint32_t*)(pl + 8)};
#pragma unroll
            for (int rt = 0; rt < 2; rt++) {
                mma_f16(acc[rt][ct], aF[rt], bH);
                mma_f16(acc[rt][ct], aF[rt], bL);
            }
        }
    }
}

// -------- GEMM (GCN layers): hs = fp16( (A@W) * dis[m] ) --------
__global__ __launch_bounds__(256, 1)
void gemm_kernel(const void* __restrict__ A, int a_fp16,
                 const __half* __restrict__ Wt, const float* __restrict__ dis,
                 __half* __restrict__ Ch, int M)
{
    extern __shared__ char smem[];
    __half* Ah = (__half*)smem;
    __half* Wh = Ah + 128 * ASTRIDE;
    __half* Wl = Wh + 128 * ASTRIDE;

    const int tid = threadIdx.x;
    const int m0  = blockIdx.x * BM;

    load_a_tile(Ah, A, a_fp16, m0, M, tid);
    load_w_tile(Wh, Wt, tid);
    load_w_tile(Wl, Wt + 16384, tid);
    __syncthreads();

    const int wid   = tid >> 5;
    const int lane  = tid & 31;
    const int rbase = (wid & 3) * 32;
    const int nbase = (wid >> 2) * 64;
    const int gr = lane >> 2;
    const int qc = (lane & 3) * 2;

    float acc[2][8][4];
#pragma unroll
    for (int rt = 0; rt < 2; rt++)
#pragma unroll
        for (int ct = 0; ct < 8; ct++)
#pragma unroll
            for (int q = 0; q < 4; q++) acc[rt][ct][q] = 0.0f;

    mma_sweep(acc, Ah, Wh, Wl, rbase, nbase, gr, qc);

#pragma unroll
    for (int rt = 0; rt < 2; rt++) {
        int m_lo = m0 + rbase + rt * 16 + gr;
        int m_hi = m_lo + 8;
        float d0 = (m_lo < M) ? dis[m_lo] : 0.f;
        float d1 = (m_hi < M) ? dis[m_hi] : 0.f;
#pragma unroll
        for (int ct = 0; ct < 8; ct++) {
            int c = nbase + ct * 8 + qc;
            float* a = acc[rt][ct];
            if (m_lo < M) {
                __half2 hv = __floats2half2_rn(a[0] * d0, a[1] * d0);
                *(uint32_t*)(Ch + (size_t)m_lo * D + c) = *(uint32_t*)&hv;
            }
            if (m_hi < M) {
                __half2 hv = __floats2half2_rn(a[2] * d1, a[3] * d1);
                *(uint32_t*)(Ch + (size_t)m_hi * D + c) = *(uint32_t*)&hv;
            }
        }
    }
}

// -------- fused MLP head: OUT = relu(A@W1 + b1) @ W2 + b2 (fp32 out) --------
__global__ __launch_bounds__(256, 1)
void mlp_kernel(const __half* __restrict__ A,
                const __half* __restrict__ W1t, const __half* __restrict__ W2t,
                const float* __restrict__ b1, const float* __restrict__ b2,
                float* __restrict__ OUT, int M)
{
    extern __shared__ char smem[];
    __half* AB  = (__half*)smem;              // A, then reused for hidden B
    __half* W1h = AB  + 128 * ASTRIDE;
    __half* W1l = W1h + 128 * ASTRIDE;
    __half* W2h = W1l + 128 * ASTRIDE;
    __half* W2l = W2h + 128 * ASTRIDE;

    const int tid = threadIdx.x;
    const int m0  = blockIdx.x * BM;

    load_a_tile(AB, A, 1, m0, M, tid);
    load_w_tile(W1h, W1t, tid);
    load_w_tile(W1l, W1t + 16384, tid);
    load_w_tile(W2h, W2t, tid);
    load_w_tile(W2l, W2t + 16384, tid);
    __syncthreads();

    const int wid   = tid >> 5;
    const int lane  = tid & 31;
    const int rbase = (wid & 3) * 32;
    const int nbase = (wid >> 2) * 64;
    const int gr = lane >> 2;
    const int qc = (lane & 3) * 2;

    float acc[2][8][4];
#pragma unroll
    for (int rt = 0; rt < 2; rt++)
#pragma unroll
        for (int ct = 0; ct < 8; ct++)
#pragma unroll
            for (int q = 0; q < 4; q++) acc[rt][ct][q] = 0.0f;

    mma_sweep(acc, AB, W1h, W1l, rbase, nbase, gr, qc);
    __syncthreads();   // all A reads done before overwrite

    // B = relu(acc + b1) -> fp16 into AB
#pragma unroll
    for (int rt = 0; rt < 2; rt++) {
        int r_lo = rbase + rt * 16 + gr;
        int r_hi = r_lo + 8;
#pragma unroll
        for (int ct = 0; ct < 8; ct++) {
            int c = nbase + ct * 8 + qc;
            float2 bb = __ldg((const float2*)(b1 + c));
            float* a = acc[rt][ct];
            __half2 v0 = __floats2half2_rn(fmaxf(a[0] + bb.x, 0.f), fmaxf(a[1] + bb.y, 0.f));
            __half2 v1 = __floats2half2_rn(fmaxf(a[2] + bb.x, 0.f), fmaxf(a[3] + bb.y, 0.f));
            *(uint32_t*)(AB + r_lo * ASTRIDE + c) = *(uint32_t*)&v0;
            *(uint32_t*)(AB + r_hi * ASTRIDE + c) = *(uint32_t*)&v1;
        }
    }
    __syncthreads();

#pragma unroll
    for (int rt = 0; rt < 2; rt++)
#pragma unroll
        for (int ct = 0; ct < 8; ct++)
#pragma unroll
            for (int q = 0; q < 4; q++) acc[rt][ct][q] = 0.0f;

    mma_sweep(acc, AB, W2h, W2l, rbase, nbase, gr, qc);

#pragma unroll
    for (int rt = 0; rt < 2; rt++) {
        int m_lo = m0 + rbase + rt * 16 + gr;
        int m_hi = m_lo + 8;
#pragma unroll
        for (int ct = 0; ct < 8; ct++) {
            int c = nbase + ct * 8 + qc;
            float2 bb = __ldg((const float2*)(b2 + c));
            float* a = acc[rt][ct];
            if (m_lo < M) *(float2*)(OUT + (size_t)m_lo * D + c) = make_float2(a[0] + bb.x, a[1] + bb.y);
            if (m_hi < M) *(float2*)(OUT + (size_t)m_hi * D + c) = make_float2(a[2] + bb.x, a[3] + bb.y);
        }
    }
}

// -------- gather: buf[v] = fp16( relu( bias + dis[v]*(hs[v] + sum hs[src]) ) ) --------
__device__ __forceinline__ void add_row(float* acc, uint4 r) {
    float2 f0 = __half22float2(*(__half2*)&r.x);
    float2 f1 = __half22float2(*(__half2*)&r.y);
    float2 f2 = __half22float2(*(__half2*)&r.z);
    float2 f3 = __half22float2(*(__half2*)&r.w);
    acc[0] += f0.x; acc[1] += f0.y; acc[2] += f1.x; acc[3] += f1.y;
    acc[4] += f2.x; acc[5] += f2.y; acc[6] += f3.x; acc[7] += f3.y;
}

__global__ void gather_kernel(const float* __restrict__ bias, __half* __restrict__ out,
                              const __half* __restrict__ h, const int* __restrict__ csrc,
                              const int* __restrict__ off, const int* __restrict__ cnt_,
                              const float* __restrict__ dis) {
    int node = blockIdx.x * 8 + (threadIdx.x >> 5);
    int lane = threadIdx.x & 31;
    int half = lane >> 4;
    int li   = lane & 15;
    if (node >= N_NODES) return;
    int beg = off[node];
    int cnt = cnt_[node];

    float acc[8] = {0.f, 0.f, 0.f, 0.f, 0.f, 0.f, 0.f, 0.f};
    if (half == 0)
        add_row(acc, __ldg((const uint4*)(h + (size_t)node * D) + li));  // self

    int j = half;
    for (; j + 6 < cnt; j += 8) {
        int s0 = __ldg(&csrc[beg + j]);
        int s1 = __ldg(&csrc[beg + j + 2]);
        int s2 = __ldg(&csrc[beg + j + 4]);
        int s3 = __ldg(&csrc[beg + j + 6]);
        uint4 r0 = __ldg((const uint4*)(h + (size_t)s0 * D) + li);
        uint4 r1 = __ldg((const uint4*)(h + (size_t)s1 * D) + li);
        uint4 r2 = __ldg((const uint4*)(h + (size_t)s2 * D) + li);
        uint4 r3 = __ldg((const uint4*)(h + (size_t)s3 * D) + li);
        add_row(acc, r0); add_row(acc, r1); add_row(acc, r2); add_row(acc, r3);
    }
    for (; j < cnt; j += 2) {
        int s = __ldg(&csrc[beg + j]);
        add_row(acc, __ldg((const uint4*)(h + (size_t)s * D) + li));
    }

#pragma unroll
    for (int k = 0; k < 8; k++)
        acc[k] += __shfl_xor_sync(0xffffffffu, acc[k], 16);

    if (half == 0) {
        float dd = __ldg(&dis[node]);
        float4 b0 = __ldg((const float4*)(bias + li * 8));
        float4 b1 = __ldg((const float4*)(bias + li * 8 + 4));
        __half2 o0 = __floats2half2_rn(fmaxf(fmaf(dd, acc[0], b0.x), 0.f),
                                       fmaxf(fmaf(dd, acc[1], b0.y), 0.f));
        __half2 o1 = __floats2half2_rn(fmaxf(fmaf(dd, acc[2], b0.z), 0.f),
                                       fmaxf(fmaf(dd, acc[3], b0.w), 0.f));
        __half2 o2 = __floats2half2_rn(fmaxf(fmaf(dd, acc[4], b1.x), 0.f),
                                       fmaxf(fmaf(dd, acc[5], b1.y), 0.f));
        __half2 o3 = __floats2half2_rn(fmaxf(fmaf(dd, acc[6], b1.z), 0.f),
                                       fmaxf(fmaf(dd, acc[7], b1.w), 0.f));
        uint4 pk;
        pk.x = *(uint32_t*)&o0; pk.y = *(uint32_t*)&o1;
        pk.z = *(uint32_t*)&o2; pk.w = *(uint32_t*)&o3;
        *((uint4*)(out + (size_t)node * D) + li) = pk;
    }
}

// -------- stream/event infra --------
struct StreamInfra {
    cudaStream_t s2;
    cudaEvent_t  e_fork, e_join;
    StreamInfra() {
        cudaStreamCreateWithFlags(&s2, cudaStreamNonBlocking);
        cudaEventCreateWithFlags(&e_fork, cudaEventDisableTiming);
        cudaEventCreateWithFlags(&e_join, cudaEventDisableTiming);
    }
};
static StreamInfra g_si;

static void build_csr(cudaStream_t st, int g, const int* src, const int* dst) {
    const int node_blocks = (N_NODES + 255) / 256;
    const int edge_blocks = (NE + 255) / 256;
    int* cnt; int* off; int* cur; int* csrc; float* dis;
    cudaGetSymbolAddress((void**)&cnt,  g_cnt);
    cudaGetSymbolAddress((void**)&off,  g_off);
    cudaGetSymbolAddress((void**)&cur,  g_cur);
    cudaGetSymbolAddress((void**)&csrc, g_csrc);
    cudaGetSymbolAddress((void**)&dis,  g_dis);
    cnt  += (size_t)g * N_NODES;
    off  += (size_t)g * N_NODES;
    cur  += (size_t)g * N_NODES;
    csrc += (size_t)g * NE;
    dis  += (size_t)g * N_NODES;

    zero_kernel<<<node_blocks, 256, 0, st>>>(cnt);
    count_kernel<<<edge_blocks, 256, 0, st>>>(dst, cnt);
    scan_fused_kernel<<<1, 1024, 0, st>>>(cnt, off, cur, dis);
    fill_kernel<<<edge_blocks, 256, 0, st>>>(src, dst, cur, csrc);
}

extern "C" void kernel_launch(void* const* d_in, const int* in_sizes, int n_in,
                              void* d_out, int out_size)
{
    const float* x    = (const float*)d_in[0];
    const int*   ei   = (const int*)  d_in[1];
    const float* xa   = (const float*)d_in[2];
    const int*   eia  = (const int*)  d_in[3];
    const float* W_in = (const float*)d_in[4];
    const float* b_in = (const float*)d_in[5];
    const float* W_h  = (const float*)d_in[6];
    const float* b_h  = (const float*)d_in[7];
    const float* W_out= (const float*)d_in[8];
    const float* b_out= (const float*)d_in[9];
    const float* Wf1  = (const float*)d_in[10];
    const float* bf1  = (const float*)d_in[11];
    const float* Wf2  = (const float*)d_in[12];
    const float* bf2  = (const float*)d_in[13];
    float* out = (float*)d_out;

    cudaFuncSetAttribute(gemm_kernel,
        cudaFuncAttributeMaxDynamicSharedMemorySize, GEMM_SMEM);
    cudaFuncSetAttribute(mlp_kernel,
        cudaFuncAttributeMaxDynamicSharedMemorySize, MLP_SMEM);

    __half *hp, *bufp, *wtp;
    cudaGetSymbolAddress((void**)&hp,   g_h);
    cudaGetSymbolAddress((void**)&bufp, g_buf);
    cudaGetSymbolAddress((void**)&wtp,  g_wt);

    const int gemm_blocks   = (N_NODES + BM - 1) / BM;
    const int gather_blocks = (N_NODES + 7) / 8;

    wprep_kernel<<<(5 * 16384 + 255) / 256, 256>>>(W_in, W_h, W_out, Wf1, Wf2);

    // CSR graph 0 on origin stream; CSR graph 1 on s2 (overlaps graph-0 compute)
    cudaEventRecord(g_si.e_fork, 0);
    cudaStreamWaitEvent(g_si.s2, g_si.e_fork, 0);
    build_csr(0,       0, ei,  ei  + NE);
    build_csr(g_si.s2, 1, eia, eia + NE);

    const float* bl[3] = {b_in, b_h, b_out};

    for (int g = 0; g < 2; g++) {
        const float* X = g ? xa : x;
        float* OUT = out + (size_t)g * N_NODES * D;

        float* dis; int* off; int* cnt; int* csrc;
        cudaGetSymbolAddress((void**)&dis,  g_dis);
        cudaGetSymbolAddress((void**)&off,  g_off);
        cudaGetSymbolAddress((void**)&cnt,  g_cnt);
        cudaGetSymbolAddress((void**)&csrc, g_csrc);
        dis  += (size_t)g * N_NODES;
        off  += (size_t)g * N_NODES;
        cnt  += (size_t)g * N_NODES;
        csrc += (size_t)g * NE;

        if (g == 1) {   // join: graph-1 CSR must be complete
            cudaEventRecord(g_si.e_join, g_si.s2);
            cudaStreamWaitEvent(0, g_si.e_join, 0);
        }

        const void* in = X;
        int a_fp16 = 0;
        for (int l = 0; l < 3; l++) {
            gemm_kernel<<<gemm_blocks, 256, GEMM_SMEM>>>(
                in, a_fp16, wtp + (size_t)l * 32768, dis, hp, N_NODES);
            gather_kernel<<<gather_blocks, 256>>>(
                bl[l], bufp, hp, csrc, off, cnt, dis);
            in = bufp;
            a_fp16 = 1;
        }
        mlp_kernel<<<gemm_blocks, 256, MLP_SMEM>>>(
            bufp, wtp + 3 * 32768, wtp + 4 * 32768, bf1, bf2, OUT, N_NODES);
    }
}

// round 16
// speedup vs baseline: 1.2863x; 1.2863x over previous
#include <cuda_runtime.h>
#include <cuda_fp16.h>
#include <cstdint>

#define N_NODES 50000
#define D 128
#define NE 800000
#define BM 128
#define SCAN_NBLK ((N_NODES + 1023) / 1024)      // 49
#define ASTRIDE 136                              // halfs per smem row
#define TILE_B (128 * ASTRIDE * 2)               // 34816 bytes per 128x128 fp16 tile
#define GEMM_SMEM (3 * TILE_B)                   // A, Wh, Wl
#define MLP_SMEM  (5 * TILE_B)                   // A/B, W1h, W1l, W2h, W2l

// -------- shared compute scratch (graphs run sequentially) --------
__device__ __half g_h[(size_t)N_NODES * D];     // hs = (A@W)*dis[row]
__device__ __half g_buf[(size_t)N_NODES * D];   // layer activations, fp16
// -------- per-graph CSR scratch (builds overlap) --------
__device__ float  g_dis[2][N_NODES];
__device__ int    g_cnt[2][N_NODES];
__device__ int    g_off[2][N_NODES];
__device__ int    g_cur[2][N_NODES];
__device__ int    g_csrc[2][NE];
__device__ int    g_bsum[2][64];
// -------- packed weights: 5 x [hi 128x128][lo 128x128] fp16, layout [n][k] --------
__device__ __half g_wt[5 * 2 * 16384];

// -------- CSR build --------
__global__ void zero_kernel(int* __restrict__ cnt) {
    int i = blockIdx.x * blockDim.x + threadIdx.x;
    if (i < N_NODES) cnt[i] = 0;
}
__global__ void count_kernel(const int* __restrict__ dst, int* __restrict__ cnt) {
    int e = blockIdx.x * blockDim.x + threadIdx.x;
    if (e < NE) atomicAdd(&cnt[dst[e]], 1);
}
__global__ void scan1_kernel(const int* __restrict__ cnt, int* __restrict__ off,
                             int* __restrict__ bsum, float* __restrict__ dis) {
    __shared__ int sh[1024];
    int i = blockIdx.x * 1024 + threadIdx.x;
    int v = (i < N_NODES) ? cnt[i] : 0;
    if (i < N_NODES) dis[i] = rsqrtf((float)v + 1.0f);
    sh[threadIdx.x] = v;
    __syncthreads();
#pragma unroll
    for (int ofs = 1; ofs < 1024; ofs <<= 1) {
        int t = (threadIdx.x >= ofs) ? sh[threadIdx.x - ofs] : 0;
        __syncthreads();
        sh[threadIdx.x] += t;
        __syncthreads();
    }
    if (i < N_NODES) off[i] = sh[threadIdx.x] - v;
    if (threadIdx.x == 1023) bsum[blockIdx.x] = sh[1023];
}
__global__ void scan2_kernel(int* __restrict__ bsum) {
    __shared__ int sh[64];
    int v = (threadIdx.x < SCAN_NBLK) ? bsum[threadIdx.x] : 0;
    sh[threadIdx.x] = v;
    __syncthreads();
#pragma unroll
    for (int ofs = 1; ofs < 64; ofs <<= 1) {
        int t = (threadIdx.x >= ofs) ? sh[threadIdx.x - ofs] : 0;
        __syncthreads();
        sh[threadIdx.x] += t;
        __syncthreads();
    }
    if (threadIdx.x < SCAN_NBLK) bsum[threadIdx.x] = sh[threadIdx.x] - v;
}
__global__ void scan3_kernel(int* __restrict__ off, const int* __restrict__ bsum,
                             int* __restrict__ cur) {
    int i = blockIdx.x * blockDim.x + threadIdx.x;
    if (i < N_NODES) {
        int o = off[i] + bsum[i >> 10];
        off[i] = o;
        cur[i] = o;
    }
}
__global__ void fill_kernel(const int* __restrict__ src, const int* __restrict__ dst,
                            int* __restrict__ cur, int* __restrict__ csrc) {
    int e = blockIdx.x * blockDim.x + threadIdx.x;
    if (e >= NE) return;
    int p = atomicAdd(&cur[dst[e]], 1);
    csrc[p] = src[e];
}

// -------- weight prep: W[k][n] fp32 -> Wt_hi[n][k], Wt_lo[n][k] fp16 --------
__global__ void wprep_kernel(const float* __restrict__ W0, const float* __restrict__ W1,
                             const float* __restrict__ W2, const float* __restrict__ W3,
                             const float* __restrict__ W4) {
    int idx = blockIdx.x * blockDim.x + threadIdx.x;
    if (idx >= 5 * 16384) return;
    int w = idx >> 14;
    int p = idx & 16383;
    int n = p >> 7;
    int k = p & 127;
    const float* W = (w == 0) ? W0 : (w == 1) ? W1 : (w == 2) ? W2 : (w == 3) ? W3 : W4;
    float v = __ldg(&W[k * 128 + n]);
    __half hi = __float2half_rn(v);
    __half lo = __float2half_rn(v - __half2float(hi));
    g_wt[(size_t)w * 32768 + n * 128 + k]         = hi;
    g_wt[(size_t)w * 32768 + 16384 + n * 128 + k] = lo;
}

// -------- f16 mma.sync (baseline sm_80+ PTX) --------
__device__ __forceinline__ void mma_f16(float* c, const uint32_t* a, const uint32_t* b) {
    asm volatile(
        "mma.sync.aligned.m16n8k16.row.col.f32.f16.f16.f32 "
        "{%0,%1,%2,%3}, {%4,%5,%6,%7}, {%8,%9}, {%0,%1,%2,%3};\n"
        : "+f"(c[0]), "+f"(c[1]), "+f"(c[2]), "+f"(c[3])
        : "r"(a[0]), "r"(a[1]), "r"(a[2]), "r"(a[3]), "r"(b[0]), "r"(b[1]));
}

__device__ __forceinline__ void load_a_tile(__half* Ah, const void* A, int a_fp16,
                                            int m0, int M, int tid) {
    if (a_fp16) {
        const __half* Af = (const __half*)A;
#pragma unroll
        for (int i = 0; i < 8; i++) {
            int f   = i * 256 + tid;
            int m   = f >> 4;
            int c16 = f & 15;
            uint4 v = make_uint4(0, 0, 0, 0);
            if (m0 + m < M)
                v = __ldg((const uint4*)(Af + (size_t)(m0 + m) * D) + c16);
            *(uint4*)((char*)Ah + m * (ASTRIDE * 2) + c16 * 16) = v;
        }
    } else {
        const float* Af = (const float*)A;
#pragma unroll
        for (int i = 0; i < 16; i++) {
            int f  = i * 256 + tid;
            int m  = f >> 5;
            int k4 = f & 31;
            float4 v = make_float4(0.f, 0.f, 0.f, 0.f);
            if (m0 + m < M) v = __ldg((const float4*)(Af + (size_t)(m0 + m) * D) + k4);
            __half2 h0 = __floats2half2_rn(v.x, v.y);
            __half2 h1 = __floats2half2_rn(v.z, v.w);
            uint2 pk;
            pk.x = *(uint32_t*)&h0; pk.y = *(uint32_t*)&h1;
            *(uint2*)((char*)Ah + m * (ASTRIDE * 2) + k4 * 8) = pk;
        }
    }
}
__device__ __forceinline__ void load_w_tile(__half* Ws, const __half* Wt, int tid) {
#pragma unroll
    for (int i = 0; i < 8; i++) {
        int f   = i * 256 + tid;
        int n   = f >> 4;
        int c16 = f & 15;
        *(uint4*)((char*)Ws + n * (ASTRIDE * 2) + c16 * 16) =
            __ldg((const uint4*)((const char*)Wt + n * 256 + c16 * 16));
    }
}
__device__ __forceinline__ void mma_sweep(float acc[2][8][4], const __half* Ah,
                                          const __half* Wh, const __half* Wl,
                                          int rbase, int nbase, int gr, int qc) {
#pragma unroll
    for (int kc = 0; kc < 8; kc++) {
        int k0 = kc * 16;
        uint32_t aF[2][4];
#pragma unroll
        for (int rt = 0; rt < 2; rt++) {
            const __half* ph = Ah + (rbase + rt * 16 + gr) * ASTRIDE + k0 + qc;
            aF[rt][0] = *(const uint32_t*)ph;
            aF[rt][1] = *(const uint32_t*)(ph + 8 * ASTRIDE);
            aF[rt][2] = *(const uint32_t*)(ph + 8);
            aF[rt][3] = *(const uint32_t*)(ph + 8 * ASTRIDE + 8);
        }
#pragma unroll
        for (int ct = 0; ct < 8; ct++) {
            int n = nbase + ct * 8 + gr;
            const __half* ph = Wh + n * ASTRIDE + k0 + qc;
            const __half* pl = Wl + n * ASTRIDE + k0 + qc;
            uint32_t bH[2] = {*(const uint32_t*)ph, *(const uint32_t*)(ph + 8)};
            uint32_t bL[2] = {*(const uint32_t*)pl, *(const uint32_t*)(pl + 8)};
#pragma unroll
            for (int rt = 0; rt < 2; rt++) {
                mma_f16(acc[rt][ct], aF[rt], bH);
                mma_f16(acc[rt][ct], aF[rt], bL);
            }
        }
    }
}

// -------- GEMM (GCN layers): hs = fp16( (A@W) * dis[m] ) --------
__global__ __launch_bounds__(256, 1)
void gemm_kernel(const void* __restrict__ A, int a_fp16,
                 const __half* __restrict__ Wt, const float* __restrict__ dis,
                 __half* __restrict__ Ch, int M)
{
    extern __shared__ char smem[];
    __half* Ah = (__half*)smem;
    __half* Wh = Ah + 128 * ASTRIDE;
    __half* Wl = Wh + 128 * ASTRIDE;

    const int tid = threadIdx.x;
    const int m0  = blockIdx.x * BM;

    load_a_tile(Ah, A, a_fp16, m0, M, tid);
    load_w_tile(Wh, Wt, tid);
    load_w_tile(Wl, Wt + 16384, tid);
    __syncthreads();

    const int wid   = tid >> 5;
    const int lane  = tid & 31;
    const int rbase = (wid & 3) * 32;
    const int nbase = (wid >> 2) * 64;
    const int gr = lane >> 2;
    const int qc = (lane & 3) * 2;

    float acc[2][8][4];
#pragma unroll
    for (int rt = 0; rt < 2; rt++)
#pragma unroll
        for (int ct = 0; ct < 8; ct++)
#pragma unroll
            for (int q = 0; q < 4; q++) acc[rt][ct][q] = 0.0f;

    mma_sweep(acc, Ah, Wh, Wl, rbase, nbase, gr, qc);

#pragma unroll
    for (int rt = 0; rt < 2; rt++) {
        int m_lo = m0 + rbase + rt * 16 + gr;
        int m_hi = m_lo + 8;
        float d0 = (m_lo < M) ? dis[m_lo] : 0.f;
        float d1 = (m_hi < M) ? dis[m_hi] : 0.f;
#pragma unroll
        for (int ct = 0; ct < 8; ct++) {
            int c = nbase + ct * 8 + qc;
            float* a = acc[rt][ct];
            if (m_lo < M) {
                __half2 hv = __floats2half2_rn(a[0] * d0, a[1] * d0);
                *(uint32_t*)(Ch + (size_t)m_lo * D + c) = *(uint32_t*)&hv;
            }
            if (m_hi < M) {
                __half2 hv = __floats2half2_rn(a[2] * d1, a[3] * d1);
                *(uint32_t*)(Ch + (size_t)m_hi * D + c) = *(uint32_t*)&hv;
            }
        }
    }
}

// -------- fused MLP head: OUT = relu(A@W1 + b1) @ W2 + b2 (fp32 out) --------
__global__ __launch_bounds__(256, 1)
void mlp_kernel(const __half* __restrict__ A,
                const __half* __restrict__ W1t, const __half* __restrict__ W2t,
                const float* __restrict__ b1, const float* __restrict__ b2,
                float* __restrict__ OUT, int M)
{
    extern __shared__ char smem[];
    __half* AB  = (__half*)smem;
    __half* W1h = AB  + 128 * ASTRIDE;
    __half* W1l = W1h + 128 * ASTRIDE;
    __half* W2h = W1l + 128 * ASTRIDE;
    __half* W2l = W2h + 128 * ASTRIDE;

    const int tid = threadIdx.x;
    const int m0  = blockIdx.x * BM;

    load_a_tile(AB, A, 1, m0, M, tid);
    load_w_tile(W1h, W1t, tid);
    load_w_tile(W1l, W1t + 16384, tid);
    load_w_tile(W2h, W2t, tid);
    load_w_tile(W2l, W2t + 16384, tid);
    __syncthreads();

    const int wid   = tid >> 5;
    const int lane  = tid & 31;
    const int rbase = (wid & 3) * 32;
    const int nbase = (wid >> 2) * 64;
    const int gr = lane >> 2;
    const int qc = (lane & 3) * 2;

    float acc[2][8][4];
#pragma unroll
    for (int rt = 0; rt < 2; rt++)
#pragma unroll
        for (int ct = 0; ct < 8; ct++)
#pragma unroll
            for (int q = 0; q < 4; q++) acc[rt][ct][q] = 0.0f;

    mma_sweep(acc, AB, W1h, W1l, rbase, nbase, gr, qc);
    __syncthreads();

#pragma unroll
    for (int rt = 0; rt < 2; rt++) {
        int r_lo = rbase + rt * 16 + gr;
        int r_hi = r_lo + 8;
#pragma unroll
        for (int ct = 0; ct < 8; ct++) {
            int c = nbase + ct * 8 + qc;
            float2 bb = __ldg((const float2*)(b1 + c));
            float* a = acc[rt][ct];
            __half2 v0 = __floats2half2_rn(fmaxf(a[0] + bb.x, 0.f), fmaxf(a[1] + bb.y, 0.f));
            __half2 v1 = __floats2half2_rn(fmaxf(a[2] + bb.x, 0.f), fmaxf(a[3] + bb.y, 0.f));
            *(uint32_t*)(AB + r_lo * ASTRIDE + c) = *(uint32_t*)&v0;
            *(uint32_t*)(AB + r_hi * ASTRIDE + c) = *(uint32_t*)&v1;
        }
    }
    __syncthreads();

#pragma unroll
    for (int rt = 0; rt < 2; rt++)
#pragma unroll
        for (int ct = 0; ct < 8; ct++)
#pragma unroll
            for (int q = 0; q < 4; q++) acc[rt][ct][q] = 0.0f;

    mma_sweep(acc, AB, W2h, W2l, rbase, nbase, gr, qc);

#pragma unroll
    for (int rt = 0; rt < 2; rt++) {
        int m_lo = m0 + rbase + rt * 16 + gr;
        int m_hi = m_lo + 8;
#pragma unroll
        for (int ct = 0; ct < 8; ct++) {
            int c = nbase + ct * 8 + qc;
            float2 bb = __ldg((const float2*)(b2 + c));
            float* a = acc[rt][ct];
            if (m_lo < M) *(float2*)(OUT + (size_t)m_lo * D + c) = make_float2(a[0] + bb.x, a[1] + bb.y);
            if (m_hi < M) *(float2*)(OUT + (size_t)m_hi * D + c) = make_float2(a[2] + bb.x, a[3] + bb.y);
        }
    }
}

// -------- gather: buf[v] = fp16( relu( bias + dis[v]*(hs[v] + sum hs[src]) ) ) --------
__device__ __forceinline__ void add_row(float* acc, uint4 r) {
    float2 f0 = __half22float2(*(__half2*)&r.x);
    float2 f1 = __half22float2(*(__half2*)&r.y);
    float2 f2 = __half22float2(*(__half2*)&r.z);
    float2 f3 = __half22float2(*(__half2*)&r.w);
    acc[0] += f0.x; acc[1] += f0.y; acc[2] += f1.x; acc[3] += f1.y;
    acc[4] += f2.x; acc[5] += f2.y; acc[6] += f3.x; acc[7] += f3.y;
}

__global__ void gather_kernel(const float* __restrict__ bias, __half* __restrict__ out,
                              const __half* __restrict__ h, const int* __restrict__ csrc,
                              const int* __restrict__ off, const int* __restrict__ cnt_,
                              const float* __restrict__ dis) {
    int node = blockIdx.x * 8 + (threadIdx.x >> 5);
    int lane = threadIdx.x & 31;
    int half = lane >> 4;
    int li   = lane & 15;
    if (node >= N_NODES) return;
    int beg = off[node];
    int cnt = cnt_[node];

    float acc[8] = {0.f, 0.f, 0.f, 0.f, 0.f, 0.f, 0.f, 0.f};
    if (half == 0)
        add_row(acc, __ldg((const uint4*)(h + (size_t)node * D) + li));

    int j = half;
    for (; j + 6 < cnt; j += 8) {
        int s0 = __ldg(&csrc[beg + j]);
        int s1 = __ldg(&csrc[beg + j + 2]);
        int s2 = __ldg(&csrc[beg + j + 4]);
        int s3 = __ldg(&csrc[beg + j + 6]);
        uint4 r0 = __ldg((const uint4*)(h + (size_t)s0 * D) + li);
        uint4 r1 = __ldg((const uint4*)(h + (size_t)s1 * D) + li);
        uint4 r2 = __ldg((const uint4*)(h + (size_t)s2 * D) + li);
        uint4 r3 = __ldg((const uint4*)(h + (size_t)s3 * D) + li);
        add_row(acc, r0); add_row(acc, r1); add_row(acc, r2); add_row(acc, r3);
    }
    for (; j < cnt; j += 2) {
        int s = __ldg(&csrc[beg + j]);
        add_row(acc, __ldg((const uint4*)(h + (size_t)s * D) + li));
    }

#pragma unroll
    for (int k = 0; k < 8; k++)
        acc[k] += __shfl_xor_sync(0xffffffffu, acc[k], 16);

    if (half == 0) {
        float dd = __ldg(&dis[node]);
        float4 b0 = __ldg((const float4*)(bias + li * 8));
        float4 b1 = __ldg((const float4*)(bias + li * 8 + 4));
        __half2 o0 = __floats2half2_rn(fmaxf(fmaf(dd, acc[0], b0.x), 0.f),
                                       fmaxf(fmaf(dd, acc[1], b0.y), 0.f));
        __half2 o1 = __floats2half2_rn(fmaxf(fmaf(dd, acc[2], b0.z), 0.f),
                                       fmaxf(fmaf(dd, acc[3], b0.w), 0.f));
        __half2 o2 = __floats2half2_rn(fmaxf(fmaf(dd, acc[4], b1.x), 0.f),
                                       fmaxf(fmaf(dd, acc[5], b1.y), 0.f));
        __half2 o3 = __floats2half2_rn(fmaxf(fmaf(dd, acc[6], b1.z), 0.f),
                                       fmaxf(fmaf(dd, acc[7], b1.w), 0.f));
        uint4 pk;
        pk.x = *(uint32_t*)&o0; pk.y = *(uint32_t*)&o1;
        pk.z = *(uint32_t*)&o2; pk.w = *(uint32_t*)&o3;
        *((uint4*)(out + (size_t)node * D) + li) = pk;
    }
}

// -------- stream/event infra --------
struct StreamInfra {
    cudaStream_t s2;
    cudaEvent_t  e_fork, e_join;
    StreamInfra() {
        cudaStreamCreateWithFlags(&s2, cudaStreamNonBlocking);
        cudaEventCreateWithFlags(&e_fork, cudaEventDisableTiming);
        cudaEventCreateWithFlags(&e_join, cudaEventDisableTiming);
    }
};
static StreamInfra g_si;

static void build_csr(cudaStream_t st, int g, const int* src, const int* dst) {
    const int node_blocks = (N_NODES + 255) / 256;
    const int edge_blocks = (NE + 255) / 256;
    int* cnt; int* off; int* cur; int* csrc; int* bsum; float* dis;
    cudaGetSymbolAddress((void**)&cnt,  g_cnt);
    cudaGetSymbolAddress((void**)&off,  g_off);
    cudaGetSymbolAddress((void**)&cur,  g_cur);
    cudaGetSymbolAddress((void**)&csrc, g_csrc);
    cudaGetSymbolAddress((void**)&bsum, g_bsum);
    cudaGetSymbolAddress((void**)&dis,  g_dis);
    cnt  += (size_t)g * N_NODES;
    off  += (size_t)g * N_NODES;
    cur  += (size_t)g * N_NODES;
    csrc += (size_t)g * NE;
    bsum += (size_t)g * 64;
    dis  += (size_t)g * N_NODES;

    zero_kernel<<<node_blocks, 256, 0, st>>>(cnt);
    count_kernel<<<edge_blocks, 256, 0, st>>>(dst, cnt);
    scan1_kernel<<<SCAN_NBLK, 1024, 0, st>>>(cnt, off, bsum, dis);
    scan2_kernel<<<1, 64, 0, st>>>(bsum);
    scan3_kernel<<<node_blocks, 256, 0, st>>>(off, bsum, cur);
    fill_kernel<<<edge_blocks, 256, 0, st>>>(src, dst, cur, csrc);
}

extern "C" void kernel_launch(void* const* d_in, const int* in_sizes, int n_in,
                              void* d_out, int out_size)
{
    const float* x    = (const float*)d_in[0];
    const int*   ei   = (const int*)  d_in[1];
    const float* xa   = (const float*)d_in[2];
    const int*   eia  = (const int*)  d_in[3];
    const float* W_in = (const float*)d_in[4];
    const float* b_in = (const float*)d_in[5];
    const float* W_h  = (const float*)d_in[6];
    const float* b_h  = (const float*)d_in[7];
    const float* W_out= (const float*)d_in[8];
    const float* b_out= (const float*)d_in[9];
    const float* Wf1  = (const float*)d_in[10];
    const float* bf1  = (const float*)d_in[11];
    const float* Wf2  = (const float*)d_in[12];
    const float* bf2  = (const float*)d_in[13];
    float* out = (float*)d_out;

    cudaFuncSetAttribute(gemm_kernel,
        cudaFuncAttributeMaxDynamicSharedMemorySize, GEMM_SMEM);
    cudaFuncSetAttribute(mlp_kernel,
        cudaFuncAttributeMaxDynamicSharedMemorySize, MLP_SMEM);

    __half *hp, *bufp, *wtp;
    cudaGetSymbolAddress((void**)&hp,   g_h);
    cudaGetSymbolAddress((void**)&bufp, g_buf);
    cudaGetSymbolAddress((void**)&wtp,  g_wt);

    const int gemm_blocks   = (N_NODES + BM - 1) / BM;
    const int gather_blocks = (N_NODES + 7) / 8;

    wprep_kernel<<<(5 * 16384 + 255) / 256, 256>>>(W_in, W_h, W_out, Wf1, Wf2);

    // CSR graph 0 on origin stream; CSR graph 1 on s2 (overlaps graph-0 compute)
    cudaEventRecord(g_si.e_fork, 0);
    cudaStreamWaitEvent(g_si.s2, g_si.e_fork, 0);
    build_csr(0,       0, ei,  ei  + NE);
    build_csr(g_si.s2, 1, eia, eia + NE);

    const float* bl[3] = {b_in, b_h, b_out};

    for (int g = 0; g < 2; g++) {
        const float* X = g ? xa : x;
        float* OUT = out + (size_t)g * N_NODES * D;

        float* dis; int* off; int* cnt; int* csrc;
        cudaGetSymbolAddress((void**)&dis,  g_dis);
        cudaGetSymbolAddress((void**)&off,  g_off);
        cudaGetSymbolAddress((void**)&cnt,  g_cnt);
        cudaGetSymbolAddress((void**)&csrc, g_csrc);
        dis  += (size_t)g * N_NODES;
        off  += (size_t)g * N_NODES;
        cnt  += (size_t)g * N_NODES;
        csrc += (size_t)g * NE;

        if (g == 1) {   // join: graph-1 CSR must be complete
            cudaEventRecord(g_si.e_join, g_si.s2);
            cudaStreamWaitEvent(0, g_si.e_join, 0);
        }

        const void* in = X;
        int a_fp16 = 0;
        for (int l = 0; l < 3; l++) {
            gemm_kernel<<<gemm_blocks, 256, GEMM_SMEM>>>(
                in, a_fp16, wtp + (size_t)l * 32768, dis, hp, N_NODES);
            gather_kernel<<<gather_blocks, 256>>>(
                bl[l], bufp, hp, csrc, off, cnt, dis);
            in = bufp;
            a_fp16 = 1;
        }
        mlp_kernel<<<gemm_blocks, 256, MLP_SMEM>>>(
            bufp, wtp + 3 * 32768, wtp + 4 * 32768, bf1, bf2, OUT, N_NODES);
    }
}

// round 17
// speedup vs baseline: 1.2933x; 1.0055x over previous
#include <cuda_runtime.h>
#include <cuda_fp16.h>
#include <cstdint>

#define N_NODES 50000
#define D 128
#define NE 800000
#define BM 128
#define SCAN_NBLK ((N_NODES + 1023) / 1024)      // 49
#define ASTRIDE 136                              // halfs per smem row
#define TILE_B (128 * ASTRIDE * 2)               // 34816 bytes per 128x128 fp16 tile
#define GEMM_SMEM (3 * TILE_B)                   // A, Wh, Wl
#define MLP_SMEM  (5 * TILE_B)                   // A/B, W1h, W1l, W2h, W2l

// -------- shared compute scratch (graphs run sequentially) --------
__device__ __half g_h[(size_t)N_NODES * D];     // hs = (A@W)*dis[row]
__device__ __half g_buf[(size_t)N_NODES * D];   // layer activations, fp16
// -------- per-graph CSR scratch (builds overlap) --------
__device__ float  g_dis[2][N_NODES];
__device__ int    g_cnt[2][N_NODES];
__device__ int    g_off[2][N_NODES];
__device__ int    g_cur[2][N_NODES];
__device__ int    g_csrc[2][NE];
__device__ int    g_bsum[2][64];
// -------- packed weights: 5 x [hi 128x128][lo 128x128] fp16, layout [n][k] --------
__device__ __half g_wt[5 * 2 * 16384];

// -------- CSR build --------
__global__ void zero_kernel(int* __restrict__ cnt) {
    int i = blockIdx.x * blockDim.x + threadIdx.x;
    if (i < N_NODES) cnt[i] = 0;
}
__global__ void count_kernel(const int* __restrict__ dst, int* __restrict__ cnt) {
    int e = blockIdx.x * blockDim.x + threadIdx.x;
    if (e < NE) atomicAdd(&cnt[dst[e]], 1);
}
__global__ void scan1_kernel(const int* __restrict__ cnt, int* __restrict__ off,
                             int* __restrict__ bsum, float* __restrict__ dis) {
    __shared__ int sh[1024];
    int i = blockIdx.x * 1024 + threadIdx.x;
    int v = (i < N_NODES) ? cnt[i] : 0;
    if (i < N_NODES) dis[i] = rsqrtf((float)v + 1.0f);
    sh[threadIdx.x] = v;
    __syncthreads();
#pragma unroll
    for (int ofs = 1; ofs < 1024; ofs <<= 1) {
        int t = (threadIdx.x >= ofs) ? sh[threadIdx.x - ofs] : 0;
        __syncthreads();
        sh[threadIdx.x] += t;
        __syncthreads();
    }
    if (i < N_NODES) off[i] = sh[threadIdx.x] - v;
    if (threadIdx.x == 1023) bsum[blockIdx.x] = sh[1023];
}
__global__ void scan2_kernel(int* __restrict__ bsum) {
    __shared__ int sh[64];
    int v = (threadIdx.x < SCAN_NBLK) ? bsum[threadIdx.x] : 0;
    sh[threadIdx.x] = v;
    __syncthreads();
#pragma unroll
    for (int ofs = 1; ofs < 64; ofs <<= 1) {
        int t = (threadIdx.x >= ofs) ? sh[threadIdx.x - ofs] : 0;
        __syncthreads();
        sh[threadIdx.x] += t;
        __syncthreads();
    }
    if (threadIdx.x < SCAN_NBLK) bsum[threadIdx.x] = sh[threadIdx.x] - v;
}
__global__ void scan3_kernel(int* __restrict__ off, const int* __restrict__ bsum,
                             int* __restrict__ cur) {
    int i = blockIdx.x * blockDim.x + threadIdx.x;
    if (i < N_NODES) {
        int o = off[i] + bsum[i >> 10];
        off[i] = o;
        cur[i] = o;
    }
}
__global__ void fill_kernel(const int* __restrict__ src, const int* __restrict__ dst,
                            int* __restrict__ cur, int* __restrict__ csrc) {
    int e = blockIdx.x * blockDim.x + threadIdx.x;
    if (e >= NE) return;
    int p = atomicAdd(&cur[dst[e]], 1);
    csrc[p] = src[e];
}

// -------- weight prep: W[k][n] fp32 -> Wt_hi[n][k], Wt_lo[n][k] fp16 --------
__global__ void wprep_kernel(const float* __restrict__ W0, const float* __restrict__ W1,
                             const float* __restrict__ W2, const float* __restrict__ W3,
                             const float* __restrict__ W4) {
    int idx = blockIdx.x * blockDim.x + threadIdx.x;
    if (idx >= 5 * 16384) return;
    int w = idx >> 14;
    int p = idx & 16383;
    int n = p >> 7;
    int k = p & 127;
    const float* W = (w == 0) ? W0 : (w == 1) ? W1 : (w == 2) ? W2 : (w == 3) ? W3 : W4;
    float v = __ldg(&W[k * 128 + n]);
    __half hi = __float2half_rn(v);
    __half lo = __float2half_rn(v - __half2float(hi));
    g_wt[(size_t)w * 32768 + n * 128 + k]         = hi;
    g_wt[(size_t)w * 32768 + 16384 + n * 128 + k] = lo;
}

// -------- f16 mma.sync (baseline sm_80+ PTX) --------
__device__ __forceinline__ void mma_f16(float* c, const uint32_t* a, const uint32_t* b) {
    asm volatile(
        "mma.sync.aligned.m16n8k16.row.col.f32.f16.f16.f32 "
        "{%0,%1,%2,%3}, {%4,%5,%6,%7}, {%8,%9}, {%0,%1,%2,%3};\n"
        : "+f"(c[0]), "+f"(c[1]), "+f"(c[2]), "+f"(c[3])
        : "r"(a[0]), "r"(a[1]), "r"(a[2]), "r"(a[3]), "r"(b[0]), "r"(b[1]));
}

__device__ __forceinline__ void load_a_tile(__half* Ah, const void* A, int a_fp16,
                                            int m0, int M, int tid) {
    if (a_fp16) {
        const __half* Af = (const __half*)A;
#pragma unroll
        for (int i = 0; i < 8; i++) {
            int f   = i * 256 + tid;
            int m   = f >> 4;
            int c16 = f & 15;
            uint4 v = make_uint4(0, 0, 0, 0);
            if (m0 + m < M)
                v = __ldg((const uint4*)(Af + (size_t)(m0 + m) * D) + c16);
            *(uint4*)((char*)Ah + m * (ASTRIDE * 2) + c16 * 16) = v;
        }
    } else {
        const float* Af = (const float*)A;
#pragma unroll
        for (int i = 0; i < 16; i++) {
            int f  = i * 256 + tid;
            int m  = f >> 5;
            int k4 = f & 31;
            float4 v = make_float4(0.f, 0.f, 0.f, 0.f);
            if (m0 + m < M) v = __ldg((const float4*)(Af + (size_t)(m0 + m) * D) + k4);
            __half2 h0 = __floats2half2_rn(v.x, v.y);
            __half2 h1 = __floats2half2_rn(v.z, v.w);
            uint2 pk;
            pk.x = *(uint32_t*)&h0; pk.y = *(uint32_t*)&h1;
            *(uint2*)((char*)Ah + m * (ASTRIDE * 2) + k4 * 8) = pk;
        }
    }
}
__device__ __forceinline__ void load_w_tile(__half* Ws, const __half* Wt, int tid) {
#pragma unroll
    for (int i = 0; i < 8; i++) {
        int f   = i * 256 + tid;
        int n   = f >> 4;
        int c16 = f & 15;
        *(uint4*)((char*)Ws + n * (ASTRIDE * 2) + c16 * 16) =
            __ldg((const uint4*)((const char*)Wt + n * 256 + c16 * 16));
    }
}
__device__ __forceinline__ void mma_sweep(float acc[2][8][4], const __half* Ah,
                                          const __half* Wh, const __half* Wl,
                                          int rbase, int nbase, int gr, int qc) {
#pragma unroll
    for (int kc = 0; kc < 8; kc++) {
        int k0 = kc * 16;
        uint32_t aF[2][4];
#pragma unroll
        for (int rt = 0; rt < 2; rt++) {
            const __half* ph = Ah + (rbase + rt * 16 + gr) * ASTRIDE + k0 + qc;
            aF[rt][0] = *(const uint32_t*)ph;
            aF[rt][1] = *(const uint32_t*)(ph + 8 * ASTRIDE);
            aF[rt][2] = *(const uint32_t*)(ph + 8);
            aF[rt][3] = *(const uint32_t*)(ph + 8 * ASTRIDE + 8);
        }
#pragma unroll
        for (int ct = 0; ct < 8; ct++) {
            int n = nbase + ct * 8 + gr;
            const __half* ph = Wh + n * ASTRIDE + k0 + qc;
            const __half* pl = Wl + n * ASTRIDE + k0 + qc;
            uint32_t bH[2] = {*(const uint32_t*)ph, *(const uint32_t*)(ph + 8)};
            uint32_t bL[2] = {*(const uint32_t*)pl, *(const uint32_t*)(pl + 8)};
#pragma unroll
            for (int rt = 0; rt < 2; rt++) {
                mma_f16(acc[rt][ct], aF[rt], bH);
                mma_f16(acc[rt][ct], aF[rt], bL);
            }
        }
    }
}

// -------- GEMM (GCN layers): hs = fp16( (A@W) * dis[m] ) --------
__global__ __launch_bounds__(256, 1)
void gemm_kernel(const void* __restrict__ A, int a_fp16,
                 const __half* __restrict__ Wt, const float* __restrict__ dis,
                 __half* __restrict__ Ch, int M)
{
    extern __shared__ char smem[];
    __half* Ah = (__half*)smem;
    __half* Wh = Ah + 128 * ASTRIDE;
    __half* Wl = Wh + 128 * ASTRIDE;

    const int tid = threadIdx.x;
    const int m0  = blockIdx.x * BM;

    load_a_tile(Ah, A, a_fp16, m0, M, tid);
    load_w_tile(Wh, Wt, tid);
    load_w_tile(Wl, Wt + 16384, tid);
    __syncthreads();

    const int wid   = tid >> 5;
    const int lane  = tid & 31;
    const int rbase = (wid & 3) * 32;
    const int nbase = (wid >> 2) * 64;
    const int gr = lane >> 2;
    const int qc = (lane & 3) * 2;

    float acc[2][8][4];
#pragma unroll
    for (int rt = 0; rt < 2; rt++)
#pragma unroll
        for (int ct = 0; ct < 8; ct++)
#pragma unroll
            for (int q = 0; q < 4; q++) acc[rt][ct][q] = 0.0f;

    mma_sweep(acc, Ah, Wh, Wl, rbase, nbase, gr, qc);

#pragma unroll
    for (int rt = 0; rt < 2; rt++) {
        int m_lo = m0 + rbase + rt * 16 + gr;
        int m_hi = m_lo + 8;
        float d0 = (m_lo < M) ? dis[m_lo] : 0.f;
        float d1 = (m_hi < M) ? dis[m_hi] : 0.f;
#pragma unroll
        for (int ct = 0; ct < 8; ct++) {
            int c = nbase + ct * 8 + qc;
            float* a = acc[rt][ct];
            if (m_lo < M) {
                __half2 hv = __floats2half2_rn(a[0] * d0, a[1] * d0);
                *(uint32_t*)(Ch + (size_t)m_lo * D + c) = *(uint32_t*)&hv;
            }
            if (m_hi < M) {
                __half2 hv = __floats2half2_rn(a[2] * d1, a[3] * d1);
                *(uint32_t*)(Ch + (size_t)m_hi * D + c) = *(uint32_t*)&hv;
            }
        }
    }
}

// -------- fused MLP head: OUT = relu(A@W1 + b1) @ W2 + b2 (fp32 out) --------
__global__ __launch_bounds__(256, 1)
void mlp_kernel(const __half* __restrict__ A,
                const __half* __restrict__ W1t, const __half* __restrict__ W2t,
                const float* __restrict__ b1, const float* __restrict__ b2,
                float* __restrict__ OUT, int M)
{
    extern __shared__ char smem[];
    __half* AB  = (__half*)smem;
    __half* W1h = AB  + 128 * ASTRIDE;
    __half* W1l = W1h + 128 * ASTRIDE;
    __half* W2h = W1l + 128 * ASTRIDE;
    __half* W2l = W2h + 128 * ASTRIDE;

    const int tid = threadIdx.x;
    const int m0  = blockIdx.x * BM;

    load_a_tile(AB, A, 1, m0, M, tid);
    load_w_tile(W1h, W1t, tid);
    load_w_tile(W1l, W1t + 16384, tid);
    load_w_tile(W2h, W2t, tid);
    load_w_tile(W2l, W2t + 16384, tid);
    __syncthreads();

    const int wid   = tid >> 5;
    const int lane  = tid & 31;
    const int rbase = (wid & 3) * 32;
    const int nbase = (wid >> 2) * 64;
    const int gr = lane >> 2;
    const int qc = (lane & 3) * 2;

    float acc[2][8][4];
#pragma unroll
    for (int rt = 0; rt < 2; rt++)
#pragma unroll
        for (int ct = 0; ct < 8; ct++)
#pragma unroll
            for (int q = 0; q < 4; q++) acc[rt][ct][q] = 0.0f;

    mma_sweep(acc, AB, W1h, W1l, rbase, nbase, gr, qc);
    __syncthreads();

#pragma unroll
    for (int rt = 0; rt < 2; rt++) {
        int r_lo = rbase + rt * 16 + gr;
        int r_hi = r_lo + 8;
#pragma unroll
        for (int ct = 0; ct < 8; ct++) {
            int c = nbase + ct * 8 + qc;
            float2 bb = __ldg((const float2*)(b1 + c));
            float* a = acc[rt][ct];
            __half2 v0 = __floats2half2_rn(fmaxf(a[0] + bb.x, 0.f), fmaxf(a[1] + bb.y, 0.f));
            __half2 v1 = __floats2half2_rn(fmaxf(a[2] + bb.x, 0.f), fmaxf(a[3] + bb.y, 0.f));
            *(uint32_t*)(AB + r_lo * ASTRIDE + c) = *(uint32_t*)&v0;
            *(uint32_t*)(AB + r_hi * ASTRIDE + c) = *(uint32_t*)&v1;
        }
    }
    __syncthreads();

#pragma unroll
    for (int rt = 0; rt < 2; rt++)
#pragma unroll
        for (int ct = 0; ct < 8; ct++)
#pragma unroll
            for (int q = 0; q < 4; q++) acc[rt][ct][q] = 0.0f;

    mma_sweep(acc, AB, W2h, W2l, rbase, nbase, gr, qc);

#pragma unroll
    for (int rt = 0; rt < 2; rt++) {
        int m_lo = m0 + rbase + rt * 16 + gr;
        int m_hi = m_lo + 8;
#pragma unroll
        for (int ct = 0; ct < 8; ct++) {
            int c = nbase + ct * 8 + qc;
            float2 bb = __ldg((const float2*)(b2 + c));
            float* a = acc[rt][ct];
            if (m_lo < M) *(float2*)(OUT + (size_t)m_lo * D + c) = make_float2(a[0] + bb.x, a[1] + bb.y);
            if (m_hi < M) *(float2*)(OUT + (size_t)m_hi * D + c) = make_float2(a[2] + bb.x, a[3] + bb.y);
        }
    }
}

// -------- gather: buf[v] = fp16( relu( bias + dis[v]*(hs[v] + sum hs[src]) ) ) --------
__device__ __forceinline__ void add_row(float* acc, uint4 r) {
    float2 f0 = __half22float2(*(__half2*)&r.x);
    float2 f1 = __half22float2(*(__half2*)&r.y);
    float2 f2 = __half22float2(*(__half2*)&r.z);
    float2 f3 = __half22float2(*(__half2*)&r.w);
    acc[0] += f0.x; acc[1] += f0.y; acc[2] += f1.x; acc[3] += f1.y;
    acc[4] += f2.x; acc[5] += f2.y; acc[6] += f3.x; acc[7] += f3.y;
}

__global__ void gather_kernel(const float* __restrict__ bias, __half* __restrict__ out,
                              const __half* __restrict__ h, const int* __restrict__ csrc,
                              const int* __restrict__ off, const int* __restrict__ cnt_,
                              const float* __restrict__ dis) {
    int node = blockIdx.x * 8 + (threadIdx.x >> 5);
    int lane = threadIdx.x & 31;
    int half = lane >> 4;
    int li   = lane & 15;
    if (node >= N_NODES) return;
    int beg = off[node];
    int cnt = cnt_[node];

    float acc[8] = {0.f, 0.f, 0.f, 0.f, 0.f, 0.f, 0.f, 0.f};
    if (half == 0)
        add_row(acc, __ldg((const uint4*)(h + (size_t)node * D) + li));

    int j = half;
    for (; j + 6 < cnt; j += 8) {
        int s0 = __ldg(&csrc[beg + j]);
        int s1 = __ldg(&csrc[beg + j + 2]);
        int s2 = __ldg(&csrc[beg + j + 4]);
        int s3 = __ldg(&csrc[beg + j + 6]);
        uint4 r0 = __ldg((const uint4*)(h + (size_t)s0 * D) + li);
        uint4 r1 = __ldg((const uint4*)(h + (size_t)s1 * D) + li);
        uint4 r2 = __ldg((const uint4*)(h + (size_t)s2 * D) + li);
        uint4 r3 = __ldg((const uint4*)(h + (size_t)s3 * D) + li);
        add_row(acc, r0); add_row(acc, r1); add_row(acc, r2); add_row(acc, r3);
    }
    for (; j < cnt; j += 2) {
        int s = __ldg(&csrc[beg + j]);
        add_row(acc, __ldg((const uint4*)(h + (size_t)s * D) + li));
    }

#pragma unroll
    for (int k = 0; k < 8; k++)
        acc[k] += __shfl_xor_sync(0xffffffffu, acc[k], 16);

    if (half == 0) {
        float dd = __ldg(&dis[node]);
        float4 b0 = __ldg((const float4*)(bias + li * 8));
        float4 b1 = __ldg((const float4*)(bias + li * 8 + 4));
        __half2 o0 = __floats2half2_rn(fmaxf(fmaf(dd, acc[0], b0.x), 0.f),
                                       fmaxf(fmaf(dd, acc[1], b0.y), 0.f));
        __half2 o1 = __floats2half2_rn(fmaxf(fmaf(dd, acc[2], b0.z), 0.f),
                                       fmaxf(fmaf(dd, acc[3], b0.w), 0.f));
        __half2 o2 = __floats2half2_rn(fmaxf(fmaf(dd, acc[4], b1.x), 0.f),
                                       fmaxf(fmaf(dd, acc[5], b1.y), 0.f));
        __half2 o3 = __floats2half2_rn(fmaxf(fmaf(dd, acc[6], b1.z), 0.f),
                                       fmaxf(fmaf(dd, acc[7], b1.w), 0.f));
        uint4 pk;
        pk.x = *(uint32_t*)&o0; pk.y = *(uint32_t*)&o1;
        pk.z = *(uint32_t*)&o2; pk.w = *(uint32_t*)&o3;
        *((uint4*)(out + (size_t)node * D) + li) = pk;
    }
}

// -------- stream/event infra --------
struct StreamInfra {
    cudaStream_t s2;
    cudaEvent_t  e_fork, e_join;
    StreamInfra() {
        cudaStreamCreateWithFlags(&s2, cudaStreamNonBlocking);
        cudaEventCreateWithFlags(&e_fork, cudaEventDisableTiming);
        cudaEventCreateWithFlags(&e_join, cudaEventDisableTiming);
    }
};
static StreamInfra g_si;

static void build_csr(cudaStream_t st, int g, const int* src, const int* dst) {
    const int node_blocks = (N_NODES + 255) / 256;
    const int edge_blocks = (NE + 255) / 256;
    int* cnt; int* off; int* cur; int* csrc; int* bsum; float* dis;
    cudaGetSymbolAddress((void**)&cnt,  g_cnt);
    cudaGetSymbolAddress((void**)&off,  g_off);
    cudaGetSymbolAddress((void**)&cur,  g_cur);
    cudaGetSymbolAddress((void**)&csrc, g_csrc);
    cudaGetSymbolAddress((void**)&bsum, g_bsum);
    cudaGetSymbolAddress((void**)&dis,  g_dis);
    cnt  += (size_t)g * N_NODES;
    off  += (size_t)g * N_NODES;
    cur  += (size_t)g * N_NODES;
    csrc += (size_t)g * NE;
    bsum += (size_t)g * 64;
    dis  += (size_t)g * N_NODES;

    zero_kernel<<<node_blocks, 256, 0, st>>>(cnt);
    count_kernel<<<edge_blocks, 256, 0, st>>>(dst, cnt);
    scan1_kernel<<<SCAN_NBLK, 1024, 0, st>>>(cnt, off, bsum, dis);
    scan2_kernel<<<1, 64, 0, st>>>(bsum);
    scan3_kernel<<<node_blocks, 256, 0, st>>>(off, bsum, cur);
    fill_kernel<<<edge_blocks, 256, 0, st>>>(src, dst, cur, csrc);
}

extern "C" void kernel_launch(void* const* d_in, const int* in_sizes, int n_in,
                              void* d_out, int out_size)
{
    const float* x    = (const float*)d_in[0];
    const int*   ei   = (const int*)  d_in[1];
    const float* xa   = (const float*)d_in[2];
    const int*   eia  = (const int*)  d_in[3];
    const float* W_in = (const float*)d_in[4];
    const float* b_in = (const float*)d_in[5];
    const float* W_h  = (const float*)d_in[6];
    const float* b_h  = (const float*)d_in[7];
    const float* W_out= (const float*)d_in[8];
    const float* b_out= (const float*)d_in[9];
    const float* Wf1  = (const float*)d_in[10];
    const float* bf1  = (const float*)d_in[11];
    const float* Wf2  = (const float*)d_in[12];
    const float* bf2  = (const float*)d_in[13];
    float* out = (float*)d_out;

    cudaFuncSetAttribute(gemm_kernel,
        cudaFuncAttributeMaxDynamicSharedMemorySize, GEMM_SMEM);
    cudaFuncSetAttribute(mlp_kernel,
        cudaFuncAttributeMaxDynamicSharedMemorySize, MLP_SMEM);

    __half *hp, *bufp, *wtp;
    cudaGetSymbolAddress((void**)&hp,   g_h);
    cudaGetSymbolAddress((void**)&bufp, g_buf);
    cudaGetSymbolAddress((void**)&wtp,  g_wt);

    const int gemm_blocks   = (N_NODES + BM - 1) / BM;
    const int gather_blocks = (N_NODES + 7) / 8;

    wprep_kernel<<<(5 * 16384 + 255) / 256, 256>>>(W_in, W_h, W_out, Wf1, Wf2);

    // CSR graph 0 on origin stream; CSR graph 1 on s2 (overlaps graph-0 compute)
    cudaEventRecord(g_si.e_fork, 0);
    cudaStreamWaitEvent(g_si.s2, g_si.e_fork, 0);
    build_csr(0,       0, ei,  ei  + NE);
    build_csr(g_si.s2, 1, eia, eia + NE);

    const float* bl[3] = {b_in, b_h, b_out};

    for (int g = 0; g < 2; g++) {
        const float* X = g ? xa : x;
        float* OUT = out + (size_t)g * N_NODES * D;

        float* dis; int* off; int* cnt; int* csrc;
        cudaGetSymbolAddress((void**)&dis,  g_dis);
        cudaGetSymbolAddress((void**)&off,  g_off);
        cudaGetSymbolAddress((void**)&cnt,  g_cnt);
        cudaGetSymbolAddress((void**)&csrc, g_csrc);
        dis  += (size_t)g * N_NODES;
        off  += (size_t)g * N_NODES;
        cnt  += (size_t)g * N_NODES;
        csrc += (size_t)g * NE;

        if (g == 1) {   // join: graph-1 CSR must be complete
            cudaEventRecord(g_si.e_join, g_si.s2);
            cudaStreamWaitEvent(0, g_si.e_join, 0);
        }

        const void* in = X;
        int a_fp16 = 0;
        for (int l = 0; l < 3; l++) {
            gemm_kernel<<<gemm_blocks, 256, GEMM_SMEM>>>(
                in, a_fp16, wtp + (size_t)l * 32768, dis, hp, N_NODES);
            gather_kernel<<<gather_blocks, 256>>>(
                bl[l], bufp, hp, csrc, off, cnt, dis);
            in = bufp;
            a_fp16 = 1;
        }
        mlp_kernel<<<gemm_blocks, 256, MLP_SMEM>>>(
            bufp, wtp + 3 * 32768, wtp + 4 * 32768, bf1, bf2, OUT, N_NODES);
    }
}